// round 15
// baseline (speedup 1.0000x reference)
#include <cuda_runtime.h>
#include <cuda_fp16.h>
#include <cstdint>

// ---------------- problem constants ----------------
#define N_TOK  16384
#define DDIM   512
#define FDIM   2048
#define NEXP   8
#define CAP    16384.0f
#define EPSV   1e-6f

#define PAD_ROWS (N_TOK + NEXP * 128)   // 17408
#define MAX_TILES (PAD_ROWS / 128)      // 136
#define GATHER_BLOCKS (PAD_ROWS / 2)    // 8704 (2 rows per 256-thread block)
#define TRANS_BLOCKS (2048 * NEXP)      // 16384

// ---------------- scratch (device globals; 16B-access aligned) ----------------
__device__ unsigned char g_expert[N_TOK];
__device__ float g_logit[N_TOK];
__device__ float g_denom_inv[NEXP];
__device__ int   g_off[NEXP + 1];
__device__ int   g_ctr[NEXP];
__device__ int   g_perm[PAD_ROWS];

__device__ __align__(256) __half g_X[(size_t)PAD_ROWS * DDIM];        // gathered x, fp16
__device__ __align__(256) __half g_H[(size_t)PAD_ROWS * FDIM];        // hidden, fp16
__device__ __align__(256) __half g_W1T[(size_t)NEXP * FDIM * DDIM];   // [E][F][D]
__device__ __align__(256) __half g_W2T[(size_t)NEXP * DDIM * FDIM];   // [E][D][F]

// ---------------- helpers ----------------
__device__ __forceinline__ uint32_t smem_to_u32(const void* smem_ptr) {
    uint32_t addr;
    asm("{ .reg .u64 tmp; cvta.to.shared.u64 tmp, %1; cvt.u32.u64 %0, tmp; }"
        : "=r"(addr) : "l"(smem_ptr));
    return addr;
}

#define SMEM_SWIZZLE_128B(byte_offset) \
    ((byte_offset) ^ (((byte_offset) >> 3) & 0x70))

__device__ __forceinline__ void cp16(uint32_t dst, const void* src) {
    asm volatile("cp.async.cg.shared.global [%0], [%1], 16;"
                 :: "r"(dst), "l"(src) : "memory");
}
#define CP_COMMIT()  asm volatile("cp.async.commit_group;" ::: "memory")
#define CP_WAIT_1()  asm volatile("cp.async.wait_group 1;" ::: "memory")
#define CP_WAIT_0()  asm volatile("cp.async.wait_group 0;" ::: "memory")

__device__ __forceinline__ void ldsm_x4(uint32_t& r0, uint32_t& r1, uint32_t& r2,
                                        uint32_t& r3, uint32_t addr) {
    asm volatile("ldmatrix.sync.aligned.m8n8.x4.shared.b16 {%0,%1,%2,%3}, [%4];"
                 : "=r"(r0), "=r"(r1), "=r"(r2), "=r"(r3) : "r"(addr));
}
__device__ __forceinline__ void mma16816(float* d, const uint32_t* a,
                                         uint32_t b0, uint32_t b1) {
    asm volatile(
        "mma.sync.aligned.m16n8k16.row.col.f32.f16.f16.f32 "
        "{%0,%1,%2,%3},{%4,%5,%6,%7},{%8,%9},{%0,%1,%2,%3};"
        : "+f"(d[0]), "+f"(d[1]), "+f"(d[2]), "+f"(d[3])
        : "r"(a[0]), "r"(a[1]), "r"(a[2]), "r"(a[3]), "r"(b0), "r"(b1));
}

// ---------------------------------------------------------------------------
// 1) router (+ perm init folded in): logits = x @ Wg^T, top-1 per token
// ---------------------------------------------------------------------------
__global__ __launch_bounds__(256) void router_kernel(const float* __restrict__ x,
                                                     const float* __restrict__ Wg) {
    int gidx = blockIdx.x * 256 + threadIdx.x;
    if (gidx < PAD_ROWS) g_perm[gidx] = -1;

    __shared__ float sWg[NEXP * DDIM];
    int tid = threadIdx.x;
    for (int i = tid; i < NEXP * DDIM; i += 256) sWg[i] = Wg[i];
    __syncthreads();

    int warp = tid >> 5, lane = tid & 31;
    int token = blockIdx.x * 8 + warp;
    if (token >= N_TOK) return;

    const float* xr = x + (size_t)token * DDIM;
    float acc[NEXP];
#pragma unroll
    for (int e = 0; e < NEXP; e++) acc[e] = 0.f;
    for (int k = lane; k < DDIM; k += 32) {
        float xv = xr[k];
#pragma unroll
        for (int e = 0; e < NEXP; e++) acc[e] += xv * sWg[e * DDIM + k];
    }
#pragma unroll
    for (int e = 0; e < NEXP; e++) {
#pragma unroll
        for (int off = 16; off > 0; off >>= 1)
            acc[e] += __shfl_xor_sync(0xFFFFFFFF, acc[e], off);
    }
    if (lane == 0) {
        int best = 0;
#pragma unroll
        for (int e = 1; e < NEXP; e++)
            if (acc[e] > acc[best]) best = e;
        g_expert[token] = (unsigned char)best;
        g_logit[token]  = acc[best];
    }
}

// ---------------------------------------------------------------------------
// 2) setup (single block, deterministic tree reduction); segments pad to 128
// ---------------------------------------------------------------------------
__global__ __launch_bounds__(256) void setup_kernel() {
    __shared__ float sden[NEXP][256];
    __shared__ int   scnt[NEXP][256];
    int tid = threadIdx.x;

    float den[NEXP]; int cnt[NEXP];
#pragma unroll
    for (int e = 0; e < NEXP; e++) { den[e] = 0.f; cnt[e] = 0; }
    for (int t = tid; t < N_TOK; t += 256) {
        int e = g_expert[t];
        den[e] += g_logit[t];
        cnt[e]++;
    }
#pragma unroll
    for (int e = 0; e < NEXP; e++) { sden[e][tid] = den[e]; scnt[e][tid] = cnt[e]; }
    __syncthreads();
    for (int s = 128; s > 0; s >>= 1) {
        if (tid < s) {
#pragma unroll
            for (int e = 0; e < NEXP; e++) {
                sden[e][tid] += sden[e][tid + s];
                scnt[e][tid] += scnt[e][tid + s];
            }
        }
        __syncthreads();
    }
    if (tid == 0) {
        int off = 0;
        for (int e = 0; e < NEXP; e++) {
            g_denom_inv[e] = CAP / (sden[e][0] + EPSV);
            g_off[e] = off;
            g_ctr[e] = off;
            off += ((scnt[e][0] + 127) >> 7) << 7;
        }
        g_off[NEXP] = off;
    }
}

// ---------------------------------------------------------------------------
// 3) scatter
// ---------------------------------------------------------------------------
__global__ void scatter_kernel() {
    int t = blockIdx.x * blockDim.x + threadIdx.x;
    if (t >= N_TOK) return;
    int e = g_expert[t];
    int pos = atomicAdd(&g_ctr[e], 1);
    g_perm[pos] = t;
}

// ---------------------------------------------------------------------------
// 4) FUSED prep: gather-x (blocks 0..GATHER_BLOCKS-1, 2 rows/block)
//               + transpose+convert W1/W2 (blocks GATHER_BLOCKS..)
//    These are independent; fusing overlaps them in one launch.
// ---------------------------------------------------------------------------
__global__ __launch_bounds__(256) void prep_kernel(const float* __restrict__ x,
                                                   const float* __restrict__ W1,
                                                   const float* __restrict__ W2) {
    __shared__ float tile[32][33];
    int b = blockIdx.x;

    if (b < GATHER_BLOCKS) {
        int r = b * 2 + (threadIdx.x >> 7);
        int t = threadIdx.x & 127;
        int tok = g_perm[r];
        float4 v = make_float4(0.f, 0.f, 0.f, 0.f);
        if (tok >= 0) v = *(const float4*)(x + (size_t)tok * DDIM + t * 4);

        __half2 h01 = __floats2half2_rn(v.x, v.y);
        __half2 h23 = __floats2half2_rn(v.z, v.w);
        uint2 hh;
        hh.x = *(uint32_t*)&h01; hh.y = *(uint32_t*)&h23;
        *(uint2*)(g_X + (size_t)r * DDIM + t * 4) = hh;
        return;
    }

    int bb = b - GATHER_BLOCKS;
    int t = bb & 2047;
    int e = bb >> 11;

    const float* in;
    __half* out;
    int R, C, c0, r0;
    if (t < 1024) {                    // W1: R=DDIM, C=FDIM
        in = W1; out = g_W1T;
        R = DDIM; C = FDIM;
        c0 = (t & 63) * 32;
        r0 = (t >> 6) * 32;
    } else {                           // W2: R=FDIM, C=DDIM
        int u = t - 1024;
        in = W2; out = g_W2T;
        R = FDIM; C = DDIM;
        c0 = (u & 15) * 32;
        r0 = (u >> 4) * 32;
    }

    int tx = threadIdx.x & 31;
    int ty8 = threadIdx.x >> 5;

    const float* src = in + ((size_t)e * R + r0) * C + c0;
#pragma unroll
    for (int i = 0; i < 32; i += 8)
        tile[ty8 + i][tx] = src[(size_t)(ty8 + i) * C + tx];
    __syncthreads();

    size_t ob = ((size_t)e * C + c0) * R + r0;
#pragma unroll
    for (int i = 0; i < 32; i += 8)
        out[ob + (size_t)(ty8 + i) * R + tx] = __float2half_rn(tile[tx][ty8 + i]);
}

// ---------------------------------------------------------------------------
// HMMA grouped GEMM, pure fp16 single pass, BM=128 x BN=256:
//   C[128 x 256 tile] = A[128 x KTOT] @ B^T  (B: [N][K] K-major)
// cp.async 3-stage pipeline, one sync per chunk; ldmatrix + mma.sync;
// 8 warps, warp tile 64 x 64 (2 m-warps x 4 n-warps); B fragments staged in
// two 32-wide n-halves per k-step (regs ~185, no spill — single fragment set
// vs R5/R6's three under bf16-3-pass).
// Rationale: smem crossbar was the wall at 64x32 (reads+writes = tensor time);
// 64x64 doubles A-fragment reuse -> crossbar load drops to ~69% of tensor time.
//   FINAL=false: A = g_X (sorted), B = W1T, epilogue relu(+b1) -> g_H fp16
//   FINAL=true : A = g_H,          B = W2T, epilogue scale*(+b2) -> scatter to out
//
// smem per stage (48KB): A 16K | B 32K
// dynamic layout: [0,512) token ids (FINAL) | [1024 + p*49152) stages (3)
// ---------------------------------------------------------------------------
#define STAGE_BYTES 49152
#define SMEM_GEMM_BYTES (1024 + 3 * STAGE_BYTES)   // 148480

template<int KTOT, bool FINAL>
__global__ __launch_bounds__(256, 1) void moe_gemm_kernel(
    const float* __restrict__ bias,   // [E][NTOT]
    float* __restrict__ fout)         // FINAL: [N_TOK][DDIM]
{
    constexpr int NTOT = FINAL ? DDIM : FDIM;
    extern __shared__ char smem[];
    uint32_t sbase = smem_to_u32(smem);
    int tid = threadIdx.x;
    int lane = tid & 31, wid = tid >> 5;

    int row0 = blockIdx.x * 128;
    int total = g_off[NEXP];
    if (row0 >= total) return;
    int e = 0;
    while (g_off[e + 1] <= row0) e++;
    int bn = blockIdx.y * 256;

    if (FINAL && tid < 128) ((int*)smem)[tid] = g_perm[row0 + tid];

    const __half* A = (FINAL ? g_H : g_X) + (size_t)row0 * KTOT;
    const __half* B = (FINAL ? g_W2T : g_W1T) + ((size_t)e * NTOT + bn) * KTOT;

    const int nC = KTOT / 64;

    // warp tile: 64 (m) x 64 (n); warps laid out 2 (m) x 4 (n)
    int wm = (wid & 1) * 64;
    int wn = (wid >> 1) * 64;

    float acc[4][8][4];
#pragma unroll
    for (int mi = 0; mi < 4; mi++)
#pragma unroll
        for (int ni = 0; ni < 8; ni++)
#pragma unroll
            for (int q = 0; q < 4; q++) acc[mi][ni][q] = 0.f;

    // --- async load of one 64-wide K chunk into stage p ---
    auto load_chunk = [&](int c, int p) {
        int kt = c * 64;
        uint32_t base = sbase + 1024 + p * STAGE_BYTES;
        // A: 128 rows -> 1024 16B units
#pragma unroll
        for (int i = 0; i < 4; i++) {
            int u = tid + i * 256;
            int r = u >> 3, s = u & 7;
            uint32_t sw = SMEM_SWIZZLE_128B((uint32_t)(r * 128 + s * 16));
            cp16(base + sw, A + (size_t)r * KTOT + kt + s * 8);
        }
        // B: 256 rows -> 2048 16B units
#pragma unroll
        for (int i = 0; i < 8; i++) {
            int u = tid + i * 256;
            int r = u >> 3, s = u & 7;
            uint32_t sw = SMEM_SWIZZLE_128B((uint32_t)(r * 128 + s * 16));
            cp16(base + 16384 + sw, B + (size_t)r * KTOT + kt + s * 8);
        }
    };

    // --- compute one staged chunk (4 k-steps of 16) ---
    auto compute_chunk = [&](int p) {
        uint32_t aB = sbase + 1024 + p * STAGE_BYTES;
        uint32_t bB = aB + 16384;
#pragma unroll
        for (int ks = 0; ks < 4; ks++) {
            int k0 = ks * 16;
            int colb = (k0 + (lane >> 4) * 8) * 2;

            uint32_t Ah[4][4];
#pragma unroll
            for (int mi = 0; mi < 4; mi++) {
                int row = wm + mi * 16 + (lane & 15);
                uint32_t off = SMEM_SWIZZLE_128B((uint32_t)(row * 128 + colb));
                ldsm_x4(Ah[mi][0], Ah[mi][1], Ah[mi][2], Ah[mi][3], aB + off);
            }
            // two 32-wide n-halves; only 8 B regs live at once
#pragma unroll
            for (int bh = 0; bh < 2; bh++) {
                uint32_t Bh[2][4];
#pragma unroll
                for (int nj = 0; nj < 2; nj++) {
                    int row = wn + bh * 32 + nj * 16 + (lane & 15);
                    uint32_t off = SMEM_SWIZZLE_128B((uint32_t)(row * 128 + colb));
                    ldsm_x4(Bh[nj][0], Bh[nj][1], Bh[nj][2], Bh[nj][3], bB + off);
                }
#pragma unroll
                for (int mi = 0; mi < 4; mi++) {
#pragma unroll
                    for (int nq = 0; nq < 4; nq++) {
                        int nj = nq >> 1;
                        int h = nq & 1;
                        mma16816(acc[mi][bh * 4 + nq], Ah[mi],
                                 Bh[nj][h], Bh[nj][2 + h]);
                    }
                }
            }
        }
    };

    // --- 3-stage pipeline, one __syncthreads per chunk ---
    load_chunk(0, 0);
    CP_COMMIT();
    if (nC > 1) { load_chunk(1, 1); CP_COMMIT(); }
    for (int c = 0; c < nC; c++) {
        if (c + 1 < nC) CP_WAIT_1(); else CP_WAIT_0();
        __syncthreads();
        if (c + 2 < nC) { load_chunk(c + 2, (c + 2) % 3); CP_COMMIT(); }
        compute_chunk(c % 3);
    }

    // --- epilogue ---
    int gq = lane >> 2;          // 0..7  (row group)
    int t4 = lane & 3;           // 0..3  (column pair)
    float dinv = FINAL ? g_denom_inv[e] : 0.f;
    const int* sTok = (const int*)smem;

#pragma unroll
    for (int mi = 0; mi < 4; mi++) {
        int rA = wm + mi * 16 + gq;       // local row for d0,d1
        int rB = rA + 8;                  // local row for d2,d3
        int tok0 = 0, tok1 = 0;
        float sc0 = 0.f, sc1 = 0.f;
        if (FINAL) {
            tok0 = sTok[rA]; tok1 = sTok[rB];
            if (tok0 >= 0) sc0 = g_logit[tok0] * dinv;
            if (tok1 >= 0) sc1 = g_logit[tok1] * dinv;
        }
#pragma unroll
        for (int ni = 0; ni < 8; ni++) {
            int gcol = bn + wn + ni * 8 + t4 * 2;
            float2 bv = __ldg((const float2*)(bias + (size_t)e * NTOT + gcol));
            float* d = acc[mi][ni];
            if (FINAL) {
                if (tok0 >= 0) {
                    float2 v = make_float2(sc0 * (d[0] + bv.x), sc0 * (d[1] + bv.y));
                    *(float2*)(fout + (size_t)tok0 * DDIM + gcol) = v;
                }
                if (tok1 >= 0) {
                    float2 v = make_float2(sc1 * (d[2] + bv.x), sc1 * (d[3] + bv.y));
                    *(float2*)(fout + (size_t)tok1 * DDIM + gcol) = v;
                }
            } else {
                float f0 = d[0] + bv.x; f0 = f0 > 0.f ? f0 : 0.f;
                float f1 = d[1] + bv.y; f1 = f1 > 0.f ? f1 : 0.f;
                float f2 = d[2] + bv.x; f2 = f2 > 0.f ? f2 : 0.f;
                float f3 = d[3] + bv.y; f3 = f3 > 0.f ? f3 : 0.f;

                __half2 h01 = __floats2half2_rn(f0, f1);
                __half2 h23 = __floats2half2_rn(f2, f3);
                *(uint32_t*)(g_H + (size_t)(row0 + rA) * FDIM + gcol) = *(uint32_t*)&h01;
                *(uint32_t*)(g_H + (size_t)(row0 + rB) * FDIM + gcol) = *(uint32_t*)&h23;
            }
        }
    }
}

// ---------------------------------------------------------------------------
extern "C" void kernel_launch(void* const* d_in, const int* in_sizes, int n_in,
                              void* d_out, int out_size) {
    const float* x  = (const float*)d_in[0];   // [N, D]
    const float* Wg = (const float*)d_in[1];   // [E, D]
    const float* W1 = (const float*)d_in[2];   // [E, D, F]
    const float* b1 = (const float*)d_in[3];   // [E, F]
    const float* W2 = (const float*)d_in[4];   // [E, F, D]
    const float* b2 = (const float*)d_in[5];   // [E, D]
    float* out = (float*)d_out;                // [N, D]

    cudaFuncSetAttribute(moe_gemm_kernel<DDIM, false>,
                         cudaFuncAttributeMaxDynamicSharedMemorySize, SMEM_GEMM_BYTES);
    cudaFuncSetAttribute(moe_gemm_kernel<FDIM, true>,
                         cudaFuncAttributeMaxDynamicSharedMemorySize, SMEM_GEMM_BYTES);

    router_kernel<<<N_TOK / 8, 256>>>(x, Wg);                       // 1 (also inits perm)
    setup_kernel<<<1, 256>>>();                                     // 2
    scatter_kernel<<<N_TOK / 256, 256>>>();                         // 3
    prep_kernel<<<GATHER_BLOCKS + TRANS_BLOCKS, 256>>>(x, W1, W2);  // 4 (gather + trans)

    moe_gemm_kernel<DDIM, false><<<dim3(MAX_TILES, FDIM / 256), 256, SMEM_GEMM_BYTES>>>(b1, nullptr);   // 5
    moe_gemm_kernel<FDIM, true><<<dim3(MAX_TILES, DDIM / 256), 256, SMEM_GEMM_BYTES>>>(b2, out);        // 6
}

// round 17
// speedup vs baseline: 1.0804x; 1.0804x over previous
#include <cuda_runtime.h>
#include <cuda_fp16.h>
#include <cstdint>

// ---------------- problem constants ----------------
#define N_TOK  16384
#define DDIM   512
#define FDIM   2048
#define NEXP   8
#define CAP    16384.0f
#define EPSV   1e-6f

#define PAD_ROWS (N_TOK + NEXP * 128)   // 17408
#define MAX_TILES (PAD_ROWS / 128)      // 136
#define GATHER_BLOCKS (PAD_ROWS / 2)    // 8704 (2 rows per 256-thread block)
#define TRANS_BLOCKS (2048 * NEXP)      // 16384

// ---------------- scratch (device globals; 16B-access aligned) ----------------
__device__ unsigned char g_expert[N_TOK];
__device__ float g_logit[N_TOK];
__device__ float g_denom_inv[NEXP];
__device__ int   g_off[NEXP + 1];
__device__ int   g_ctr[NEXP];
__device__ int   g_perm[PAD_ROWS];

__device__ __align__(256) __half g_X[(size_t)PAD_ROWS * DDIM];        // gathered x, fp16
__device__ __align__(256) __half g_H[(size_t)PAD_ROWS * FDIM];        // hidden, fp16
__device__ __align__(256) __half g_W1T[(size_t)NEXP * FDIM * DDIM];   // [E][F][D]
__device__ __align__(256) __half g_W2T[(size_t)NEXP * DDIM * FDIM];   // [E][D][F]

// ---------------- helpers ----------------
__device__ __forceinline__ uint32_t smem_to_u32(const void* smem_ptr) {
    uint32_t addr;
    asm("{ .reg .u64 tmp; cvta.to.shared.u64 tmp, %1; cvt.u32.u64 %0, tmp; }"
        : "=r"(addr) : "l"(smem_ptr));
    return addr;
}

#define SMEM_SWIZZLE_128B(byte_offset) \
    ((byte_offset) ^ (((byte_offset) >> 3) & 0x70))

__device__ __forceinline__ void cp16(uint32_t dst, const void* src) {
    asm volatile("cp.async.cg.shared.global [%0], [%1], 16;"
                 :: "r"(dst), "l"(src) : "memory");
}
#define CP_COMMIT()  asm volatile("cp.async.commit_group;" ::: "memory")
#define CP_WAIT_1()  asm volatile("cp.async.wait_group 1;" ::: "memory")
#define CP_WAIT_0()  asm volatile("cp.async.wait_group 0;" ::: "memory")

__device__ __forceinline__ void ldsm_x4(uint32_t& r0, uint32_t& r1, uint32_t& r2,
                                        uint32_t& r3, uint32_t addr) {
    asm volatile("ldmatrix.sync.aligned.m8n8.x4.shared.b16 {%0,%1,%2,%3}, [%4];"
                 : "=r"(r0), "=r"(r1), "=r"(r2), "=r"(r3) : "r"(addr));
}
__device__ __forceinline__ void ldsm_x2(uint32_t& r0, uint32_t& r1, uint32_t addr) {
    asm volatile("ldmatrix.sync.aligned.m8n8.x2.shared.b16 {%0,%1}, [%2];"
                 : "=r"(r0), "=r"(r1) : "r"(addr));
}
__device__ __forceinline__ void mma16816(float* d, const uint32_t* a,
                                         uint32_t b0, uint32_t b1) {
    asm volatile(
        "mma.sync.aligned.m16n8k16.row.col.f32.f16.f16.f32 "
        "{%0,%1,%2,%3},{%4,%5,%6,%7},{%8,%9},{%0,%1,%2,%3};"
        : "+f"(d[0]), "+f"(d[1]), "+f"(d[2]), "+f"(d[3])
        : "r"(a[0]), "r"(a[1]), "r"(a[2]), "r"(a[3]), "r"(b0), "r"(b1));
}

// ---------------------------------------------------------------------------
// 1) router (+ perm init folded in): logits = x @ Wg^T, top-1 per token
// ---------------------------------------------------------------------------
__global__ __launch_bounds__(256) void router_kernel(const float* __restrict__ x,
                                                     const float* __restrict__ Wg) {
    int gidx = blockIdx.x * 256 + threadIdx.x;
    if (gidx < PAD_ROWS) g_perm[gidx] = -1;

    __shared__ float sWg[NEXP * DDIM];
    int tid = threadIdx.x;
    for (int i = tid; i < NEXP * DDIM; i += 256) sWg[i] = Wg[i];
    __syncthreads();

    int warp = tid >> 5, lane = tid & 31;
    int token = blockIdx.x * 8 + warp;
    if (token >= N_TOK) return;

    const float* xr = x + (size_t)token * DDIM;
    float acc[NEXP];
#pragma unroll
    for (int e = 0; e < NEXP; e++) acc[e] = 0.f;
    for (int k = lane; k < DDIM; k += 32) {
        float xv = xr[k];
#pragma unroll
        for (int e = 0; e < NEXP; e++) acc[e] += xv * sWg[e * DDIM + k];
    }
#pragma unroll
    for (int e = 0; e < NEXP; e++) {
#pragma unroll
        for (int off = 16; off > 0; off >>= 1)
            acc[e] += __shfl_xor_sync(0xFFFFFFFF, acc[e], off);
    }
    if (lane == 0) {
        int best = 0;
#pragma unroll
        for (int e = 1; e < NEXP; e++)
            if (acc[e] > acc[best]) best = e;
        g_expert[token] = (unsigned char)best;
        g_logit[token]  = acc[best];
    }
}

// ---------------------------------------------------------------------------
// 2) setup (single block, deterministic tree reduction); segments pad to 128
// ---------------------------------------------------------------------------
__global__ __launch_bounds__(256) void setup_kernel() {
    __shared__ float sden[NEXP][256];
    __shared__ int   scnt[NEXP][256];
    int tid = threadIdx.x;

    float den[NEXP]; int cnt[NEXP];
#pragma unroll
    for (int e = 0; e < NEXP; e++) { den[e] = 0.f; cnt[e] = 0; }
    for (int t = tid; t < N_TOK; t += 256) {
        int e = g_expert[t];
        den[e] += g_logit[t];
        cnt[e]++;
    }
#pragma unroll
    for (int e = 0; e < NEXP; e++) { sden[e][tid] = den[e]; scnt[e][tid] = cnt[e]; }
    __syncthreads();
    for (int s = 128; s > 0; s >>= 1) {
        if (tid < s) {
#pragma unroll
            for (int e = 0; e < NEXP; e++) {
                sden[e][tid] += sden[e][tid + s];
                scnt[e][tid] += scnt[e][tid + s];
            }
        }
        __syncthreads();
    }
    if (tid == 0) {
        int off = 0;
        for (int e = 0; e < NEXP; e++) {
            g_denom_inv[e] = CAP / (sden[e][0] + EPSV);
            g_off[e] = off;
            g_ctr[e] = off;
            off += ((scnt[e][0] + 127) >> 7) << 7;
        }
        g_off[NEXP] = off;
    }
}

// ---------------------------------------------------------------------------
// 3) scatter
// ---------------------------------------------------------------------------
__global__ void scatter_kernel() {
    int t = blockIdx.x * blockDim.x + threadIdx.x;
    if (t >= N_TOK) return;
    int e = g_expert[t];
    int pos = atomicAdd(&g_ctr[e], 1);
    g_perm[pos] = t;
}

// ---------------------------------------------------------------------------
// 4) FUSED prep: gather-x (blocks 0..GATHER_BLOCKS-1, 2 rows/block)
//               + transpose+convert W1/W2 (blocks GATHER_BLOCKS..)
//    Transpose loads use float4 (4x fewer LDG; prep was issue/alu-bound).
// ---------------------------------------------------------------------------
__global__ __launch_bounds__(256) void prep_kernel(const float* __restrict__ x,
                                                   const float* __restrict__ W1,
                                                   const float* __restrict__ W2) {
    __shared__ float tile[32][33];
    int b = blockIdx.x;

    if (b < GATHER_BLOCKS) {
        int r = b * 2 + (threadIdx.x >> 7);
        int t = threadIdx.x & 127;
        int tok = g_perm[r];
        float4 v = make_float4(0.f, 0.f, 0.f, 0.f);
        if (tok >= 0) v = *(const float4*)(x + (size_t)tok * DDIM + t * 4);

        __half2 h01 = __floats2half2_rn(v.x, v.y);
        __half2 h23 = __floats2half2_rn(v.z, v.w);
        uint2 hh;
        hh.x = *(uint32_t*)&h01; hh.y = *(uint32_t*)&h23;
        *(uint2*)(g_X + (size_t)r * DDIM + t * 4) = hh;
        return;
    }

    int bb = b - GATHER_BLOCKS;
    int t = bb & 2047;
    int e = bb >> 11;

    const float* in;
    __half* out;
    int R, C, c0, r0;
    if (t < 1024) {                    // W1: R=DDIM, C=FDIM
        in = W1; out = g_W1T;
        R = DDIM; C = FDIM;
        c0 = (t & 63) * 32;
        r0 = (t >> 6) * 32;
    } else {                           // W2: R=FDIM, C=DDIM
        int u = t - 1024;
        in = W2; out = g_W2T;
        R = FDIM; C = DDIM;
        c0 = (u & 15) * 32;
        r0 = (u >> 4) * 32;
    }

    // float4 loads: 256 threads x 1 float4 = 1024 floats = full 32x32 tile
    {
        int row = threadIdx.x >> 3;          // 0..31
        int cc  = (threadIdx.x & 7) * 4;     // 0,4,..28
        float4 v = *(const float4*)(in + ((size_t)e * R + r0 + row) * C + c0 + cc);
        tile[row][cc + 0] = v.x;
        tile[row][cc + 1] = v.y;
        tile[row][cc + 2] = v.z;
        tile[row][cc + 3] = v.w;
    }
    __syncthreads();

    int tx = threadIdx.x & 31;
    int ty8 = threadIdx.x >> 5;
    size_t ob = ((size_t)e * C + c0) * R + r0;
#pragma unroll
    for (int i = 0; i < 32; i += 8)
        out[ob + (size_t)(ty8 + i) * R + tx] = __float2half_rn(tile[tx][ty8 + i]);
}

// ---------------------------------------------------------------------------
// HMMA grouped GEMM (R14 champion config, verbatim):
// pure fp16 single pass, BM=128 x BN=128, 2 CTAs/SM via __launch_bounds__(256,2);
// cp.async 3-stage pipeline, one sync per chunk; ldmatrix + mma.sync;
// 8 warps, warp tile 64 x 32 (2 m-warps x 4 n-warps).
//   FINAL=false: A = g_X (sorted), B = W1T, epilogue relu(+b1) -> g_H fp16
//   FINAL=true : A = g_H,          B = W2T, epilogue scale*(+b2) -> scatter to out
//
// smem per stage (32KB): A 16K | B 16K
// dynamic layout: [0,512) token ids (FINAL) | [1024 + p*32768) stages (3)
// total 97KB/CTA -> 194KB for 2 CTAs (fits 227KB)
// ---------------------------------------------------------------------------
#define STAGE_BYTES 32768
#define SMEM_GEMM_BYTES (1024 + 3 * STAGE_BYTES)   // 99328

template<int KTOT, bool FINAL>
__global__ __launch_bounds__(256, 2) void moe_gemm_kernel(
    const float* __restrict__ bias,   // [E][NTOT]
    float* __restrict__ fout)         // FINAL: [N_TOK][DDIM]
{
    constexpr int NTOT = FINAL ? DDIM : FDIM;
    extern __shared__ char smem[];
    uint32_t sbase = smem_to_u32(smem);
    int tid = threadIdx.x;
    int lane = tid & 31, wid = tid >> 5;

    int row0 = blockIdx.x * 128;
    int total = g_off[NEXP];
    if (row0 >= total) return;
    int e = 0;
    while (g_off[e + 1] <= row0) e++;
    int bn = blockIdx.y * 128;

    if (FINAL && tid < 128) ((int*)smem)[tid] = g_perm[row0 + tid];

    const __half* A = (FINAL ? g_H : g_X) + (size_t)row0 * KTOT;
    const __half* B = (FINAL ? g_W2T : g_W1T) + ((size_t)e * NTOT + bn) * KTOT;

    const int nC = KTOT / 64;

    // warp tile: 64 (m) x 32 (n); warps laid out 2 (m) x 4 (n)
    int wm = (wid & 1) * 64;
    int wn = (wid >> 1) * 32;

    float acc[4][4][4];
#pragma unroll
    for (int mi = 0; mi < 4; mi++)
#pragma unroll
        for (int ni = 0; ni < 4; ni++)
#pragma unroll
            for (int q = 0; q < 4; q++) acc[mi][ni][q] = 0.f;

    // --- async load of one 64-wide K chunk into stage p ---
    auto load_chunk = [&](int c, int p) {
        int kt = c * 64;
        uint32_t base = sbase + 1024 + p * STAGE_BYTES;
#pragma unroll
        for (int i = 0; i < 4; i++) {
            int u = tid + i * 256;          // 0..1023
            int r = u >> 3, s = u & 7;      // row, 16B-chunk
            uint32_t sw = SMEM_SWIZZLE_128B((uint32_t)(r * 128 + s * 16));
            size_t goff = (size_t)r * KTOT + kt + s * 8;
            cp16(base +         sw, A + goff);
            cp16(base + 16384 + sw, B + goff);
        }
    };

    // --- compute one staged chunk (4 k-steps of 16) ---
    auto compute_chunk = [&](int p) {
        uint32_t aB = sbase + 1024 + p * STAGE_BYTES;
        uint32_t bB = aB + 16384;
#pragma unroll
        for (int ks = 0; ks < 4; ks++) {
            int k0 = ks * 16;
            uint32_t Ah[4][4];
#pragma unroll
            for (int mi = 0; mi < 4; mi++) {
                int row = wm + mi * 16 + (lane & 15);
                int colb = (k0 + (lane >> 4) * 8) * 2;
                uint32_t off = SMEM_SWIZZLE_128B((uint32_t)(row * 128 + colb));
                ldsm_x4(Ah[mi][0], Ah[mi][1], Ah[mi][2], Ah[mi][3], aB + off);
            }
            uint32_t Bh[4][2];
#pragma unroll
            for (int ni = 0; ni < 4; ni++) {
                int row = wn + ni * 8 + (lane & 7);
                int colb = (k0 + ((lane >> 3) & 1) * 8) * 2;
                uint32_t off = SMEM_SWIZZLE_128B((uint32_t)(row * 128 + colb));
                ldsm_x2(Bh[ni][0], Bh[ni][1], bB + off);
            }
#pragma unroll
            for (int mi = 0; mi < 4; mi++)
#pragma unroll
                for (int ni = 0; ni < 4; ni++)
                    mma16816(acc[mi][ni], Ah[mi], Bh[ni][0], Bh[ni][1]);
        }
    };

    // --- 3-stage pipeline, one __syncthreads per chunk ---
    load_chunk(0, 0);
    CP_COMMIT();
    if (nC > 1) { load_chunk(1, 1); CP_COMMIT(); }
    for (int c = 0; c < nC; c++) {
        if (c + 1 < nC) CP_WAIT_1(); else CP_WAIT_0();
        __syncthreads();
        if (c + 2 < nC) { load_chunk(c + 2, (c + 2) % 3); CP_COMMIT(); }
        compute_chunk(c % 3);
    }

    // --- epilogue ---
    int gq = lane >> 2;          // 0..7  (row group)
    int t4 = lane & 3;           // 0..3  (column pair)
    float dinv = FINAL ? g_denom_inv[e] : 0.f;
    const int* sTok = (const int*)smem;

#pragma unroll
    for (int mi = 0; mi < 4; mi++) {
        int rA = wm + mi * 16 + gq;       // local row for d0,d1
        int rB = rA + 8;                  // local row for d2,d3
        int tok0 = 0, tok1 = 0;
        float sc0 = 0.f, sc1 = 0.f;
        if (FINAL) {
            tok0 = sTok[rA]; tok1 = sTok[rB];
            if (tok0 >= 0) sc0 = g_logit[tok0] * dinv;
            if (tok1 >= 0) sc1 = g_logit[tok1] * dinv;
        }
#pragma unroll
        for (int ni = 0; ni < 4; ni++) {
            int gcol = bn + wn + ni * 8 + t4 * 2;
            float2 bv = __ldg((const float2*)(bias + (size_t)e * NTOT + gcol));
            float* d = acc[mi][ni];
            if (FINAL) {
                if (tok0 >= 0) {
                    float2 v = make_float2(sc0 * (d[0] + bv.x), sc0 * (d[1] + bv.y));
                    *(float2*)(fout + (size_t)tok0 * DDIM + gcol) = v;
                }
                if (tok1 >= 0) {
                    float2 v = make_float2(sc1 * (d[2] + bv.x), sc1 * (d[3] + bv.y));
                    *(float2*)(fout + (size_t)tok1 * DDIM + gcol) = v;
                }
            } else {
                float f0 = d[0] + bv.x; f0 = f0 > 0.f ? f0 : 0.f;
                float f1 = d[1] + bv.y; f1 = f1 > 0.f ? f1 : 0.f;
                float f2 = d[2] + bv.x; f2 = f2 > 0.f ? f2 : 0.f;
                float f3 = d[3] + bv.y; f3 = f3 > 0.f ? f3 : 0.f;

                __half2 h01 = __floats2half2_rn(f0, f1);
                __half2 h23 = __floats2half2_rn(f2, f3);
                *(uint32_t*)(g_H + (size_t)(row0 + rA) * FDIM + gcol) = *(uint32_t*)&h01;
                *(uint32_t*)(g_H + (size_t)(row0 + rB) * FDIM + gcol) = *(uint32_t*)&h23;
            }
        }
    }
}

// ---------------------------------------------------------------------------
extern "C" void kernel_launch(void* const* d_in, const int* in_sizes, int n_in,
                              void* d_out, int out_size) {
    const float* x  = (const float*)d_in[0];   // [N, D]
    const float* Wg = (const float*)d_in[1];   // [E, D]
    const float* W1 = (const float*)d_in[2];   // [E, D, F]
    const float* b1 = (const float*)d_in[3];   // [E, F]
    const float* W2 = (const float*)d_in[4];   // [E, F, D]
    const float* b2 = (const float*)d_in[5];   // [E, D]
    float* out = (float*)d_out;                // [N, D]

    cudaFuncSetAttribute(moe_gemm_kernel<DDIM, false>,
                         cudaFuncAttributeMaxDynamicSharedMemorySize, SMEM_GEMM_BYTES);
    cudaFuncSetAttribute(moe_gemm_kernel<FDIM, true>,
                         cudaFuncAttributeMaxDynamicSharedMemorySize, SMEM_GEMM_BYTES);

    router_kernel<<<N_TOK / 8, 256>>>(x, Wg);                       // 1 (also inits perm)
    setup_kernel<<<1, 256>>>();                                     // 2
    scatter_kernel<<<N_TOK / 256, 256>>>();                         // 3
    prep_kernel<<<GATHER_BLOCKS + TRANS_BLOCKS, 256>>>(x, W1, W2);  // 4 (gather + trans)

    moe_gemm_kernel<DDIM, false><<<dim3(MAX_TILES, FDIM / 128), 256, SMEM_GEMM_BYTES>>>(b1, nullptr);   // 5
    moe_gemm_kernel<FDIM, true><<<dim3(MAX_TILES, DDIM / 128), 256, SMEM_GEMM_BYTES>>>(b2, out);        // 6
}